// round 4
// baseline (speedup 1.0000x reference)
#include <cuda_runtime.h>
#include <cuda_bf16.h>
#include <cstdint>

#define B_   4
#define T_   2048
#define HIN_ 1024
#define H_   16
#define E_   64
#define HE_  (H_ * E_)   // 1024
#define BT_  (B_ * T_)   // 8192

// ---------------------------------------------------------------------------
// Persistent scratch (no runtime allocations allowed).
// ---------------------------------------------------------------------------
__device__ float g_Q[BT_ * HE_];
__device__ float g_K[BT_ * HE_];
__device__ float g_V[BT_ * HE_];

__device__ __nv_bfloat16 g_Ahi_q[BT_ * HIN_];
__device__ __nv_bfloat16 g_Alo_q[BT_ * HIN_];
__device__ __nv_bfloat16 g_Ahi_kv[BT_ * HIN_];
__device__ __nv_bfloat16 g_Alo_kv[BT_ * HIN_];
__device__ __nv_bfloat16 g_WThi[3 * HIN_ * HE_];   // W^T, [n][k] K-major
__device__ __nv_bfloat16 g_WTlo[3 * HIN_ * HE_];

// ---------------------------------------------------------------------------
// mma.sync helpers (sm_80-compatible PTX; runs on Blackwell tensor pipe)
// ---------------------------------------------------------------------------
__device__ __forceinline__ uint32_t smem_u32(const void* p) {
    uint32_t a;
    asm("{ .reg .u64 t; cvta.to.shared.u64 t, %1; cvt.u32.u64 %0, t; }"
        : "=r"(a) : "l"(p));
    return a;
}

__device__ __forceinline__ void ldsm_x4(uint32_t& r0, uint32_t& r1,
                                        uint32_t& r2, uint32_t& r3,
                                        uint32_t addr) {
    asm volatile("ldmatrix.sync.aligned.m8n8.x4.shared.b16 {%0,%1,%2,%3}, [%4];"
                 : "=r"(r0), "=r"(r1), "=r"(r2), "=r"(r3) : "r"(addr));
}

__device__ __forceinline__ void ldsm_x2(uint32_t& r0, uint32_t& r1,
                                        uint32_t addr) {
    asm volatile("ldmatrix.sync.aligned.m8n8.x2.shared.b16 {%0,%1}, [%2];"
                 : "=r"(r0), "=r"(r1) : "r"(addr));
}

__device__ __forceinline__ void mma_bf16(float* c, const uint32_t* a,
                                         const uint32_t* b) {
    asm volatile(
        "mma.sync.aligned.m16n8k16.row.col.f32.bf16.bf16.f32 "
        "{%0,%1,%2,%3}, {%4,%5,%6,%7}, {%8,%9}, {%0,%1,%2,%3};"
        : "+f"(c[0]), "+f"(c[1]), "+f"(c[2]), "+f"(c[3])
        : "r"(a[0]), "r"(a[1]), "r"(a[2]), "r"(a[3]), "r"(b[0]), "r"(b[1]));
}

// ---------------------------------------------------------------------------
// Conversion kernels: fp32 -> (hi, lo) bf16 split
// ---------------------------------------------------------------------------
__global__ __launch_bounds__(256) void split_act(const float4* __restrict__ in,
                                                 int which, int n4) {
    __nv_bfloat162* hi = (__nv_bfloat162*)((which == 0) ? g_Ahi_q : g_Ahi_kv);
    __nv_bfloat162* lo = (__nv_bfloat162*)((which == 0) ? g_Alo_q : g_Alo_kv);
    int i = blockIdx.x * blockDim.x + threadIdx.x;
    if (i >= n4) return;
    float4 v = in[i];
    __nv_bfloat16 h0 = __float2bfloat16(v.x);
    __nv_bfloat16 h1 = __float2bfloat16(v.y);
    __nv_bfloat16 h2 = __float2bfloat16(v.z);
    __nv_bfloat16 h3 = __float2bfloat16(v.w);
    __nv_bfloat162 a, b, c, d;
    a.x = h0; a.y = h1; b.x = h2; b.y = h3;
    c.x = __float2bfloat16(v.x - __bfloat162float(h0));
    c.y = __float2bfloat16(v.y - __bfloat162float(h1));
    d.x = __float2bfloat16(v.z - __bfloat162float(h2));
    d.y = __float2bfloat16(v.w - __bfloat162float(h3));
    hi[2 * i] = a; hi[2 * i + 1] = b;
    lo[2 * i] = c; lo[2 * i + 1] = d;
}

// W [K=1024, N=1024] row-major -> W^T [N, K] K-major, split hi/lo
__global__ __launch_bounds__(256) void transpose_split(const float* __restrict__ W,
                                                       int sel) {
    __shared__ float t[32][33];
    __nv_bfloat16* Thi = g_WThi + (size_t)sel * (HIN_ * HE_);
    __nv_bfloat16* Tlo = g_WTlo + (size_t)sel * (HIN_ * HE_);
    int tx = threadIdx.x, ty = threadIdx.y;
    int x = blockIdx.x * 32 + tx;
#pragma unroll
    for (int j = 0; j < 4; j++) {
        int y = blockIdx.y * 32 + ty + j * 8;
        t[ty + j * 8][tx] = W[(size_t)y * HE_ + x];
    }
    __syncthreads();
    int x2 = blockIdx.y * 32 + tx;
#pragma unroll
    for (int j = 0; j < 4; j++) {
        int y2 = blockIdx.x * 32 + ty + j * 8;
        float v = t[tx][ty + j * 8];
        __nv_bfloat16 h = __float2bfloat16(v);
        Thi[(size_t)y2 * HIN_ + x2] = h;
        Tlo[(size_t)y2 * HIN_ + x2] = __float2bfloat16(v - __bfloat162float(h));
    }
}

// ---------------------------------------------------------------------------
// Tensor-core projection: C[8192,1024] = A @ W via 3 bf16-split products.
// 128x128 CTA tile, BK=32, 8 warps (2m x 4n), warp tile 64x32.
// A row-major [m][k], B = W^T K-major [n][k] (= col-major for mma row.col).
// ---------------------------------------------------------------------------
#define BKP 40   // padded BK in bf16 elems (80B rows -> conflict-free ldmatrix)

__global__ __launch_bounds__(256) void proj_mma(int sel, float scale) {
    __shared__ __nv_bfloat16 As[128][BKP];
    __shared__ __nv_bfloat16 Bs[128][BKP];

    const int tid = threadIdx.x;
    const int warp = tid >> 5;
    const int lane = tid & 31;
    const int wm = (warp & 1) * 64;    // warp m offset
    const int wn = (warp >> 1) * 32;   // warp n offset
    const int bm = blockIdx.y << 7;
    const int bn = blockIdx.x << 7;

    const __nv_bfloat16* Ahi = (sel == 0) ? g_Ahi_q : g_Ahi_kv;
    const __nv_bfloat16* Alo = (sel == 0) ? g_Alo_q : g_Alo_kv;
    const __nv_bfloat16* Whi = g_WThi + (size_t)sel * (HIN_ * HE_);
    const __nv_bfloat16* Wlo = g_WTlo + (size_t)sel * (HIN_ * HE_);
    float* C = (sel == 0) ? g_Q : (sel == 1) ? g_K : g_V;

    const __nv_bfloat16* Aps[3] = {Ahi, Ahi, Alo};
    const __nv_bfloat16* Bps[3] = {Whi, Wlo, Whi};

    // loader: thread -> (row = tid/2, 16 elems at col (tid&1)*16)
    const int lr = tid >> 1;
    const int lc = (tid & 1) << 4;

    float acc[4][4][4];
#pragma unroll
    for (int i = 0; i < 4; i++)
#pragma unroll
        for (int j = 0; j < 4; j++)
#pragma unroll
            for (int k = 0; k < 4; k++) acc[i][j][k] = 0.f;

    // Precompute ldmatrix smem addresses (depend only on lane)
    uint32_t a_addr[4], b_addr[4];
#pragma unroll
    for (int mf = 0; mf < 4; mf++)
        a_addr[mf] = smem_u32(&As[wm + mf * 16 + (lane & 15)][(lane >> 4) * 8]);
    const int lb = lane & 15;
#pragma unroll
    for (int nf = 0; nf < 4; nf++)
        b_addr[nf] = smem_u32(&Bs[wn + nf * 8 + (lb & 7)][((lb >> 3) & 1) * 8]);

    for (int sp = 0; sp < 3; sp++) {
        const __nv_bfloat16* Ap = Aps[sp] + (size_t)(bm + lr) * HIN_ + lc;
        const __nv_bfloat16* Bp = Bps[sp] + (size_t)(bn + lr) * HIN_ + lc;
        for (int k0 = 0; k0 < HIN_; k0 += 32) {
            __syncthreads();
            *(uint4*)&As[lr][lc + 0] = *(const uint4*)(Ap + k0);
            *(uint4*)&As[lr][lc + 8] = *(const uint4*)(Ap + k0 + 8);
            *(uint4*)&Bs[lr][lc + 0] = *(const uint4*)(Bp + k0);
            *(uint4*)&Bs[lr][lc + 8] = *(const uint4*)(Bp + k0 + 8);
            __syncthreads();

#pragma unroll
            for (int kk = 0; kk < 2; kk++) {   // two k16 steps per BK=32
                const uint32_t koff = kk * 16 * 2;   // bytes within row
                uint32_t af[4][4], bf[4][2];
#pragma unroll
                for (int mf = 0; mf < 4; mf++)
                    ldsm_x4(af[mf][0], af[mf][1], af[mf][2], af[mf][3],
                            a_addr[mf] + koff);
#pragma unroll
                for (int nf = 0; nf < 4; nf++)
                    ldsm_x2(bf[nf][0], bf[nf][1], b_addr[nf] + koff);
#pragma unroll
                for (int mf = 0; mf < 4; mf++)
#pragma unroll
                    for (int nf = 0; nf < 4; nf++)
                        mma_bf16(acc[mf][nf], af[mf], bf[nf]);
            }
        }
    }

    // Epilogue: direct global stores (float2 per fragment half), scaled
    const int er = lane >> 2;         // row within 8-group
    const int ec = (lane & 3) << 1;   // col pair
#pragma unroll
    for (int mf = 0; mf < 4; mf++) {
#pragma unroll
        for (int nf = 0; nf < 4; nf++) {
            float* c0 = C + (size_t)(bm + wm + mf * 16 + er) * HE_ +
                        bn + wn + nf * 8 + ec;
            c0[0] = acc[mf][nf][0] * scale;
            c0[1] = acc[mf][nf][1] * scale;
            float* c1 = c0 + 8 * HE_;
            c1[0] = acc[mf][nf][2] * scale;
            c1[1] = acc[mf][nf][3] * scale;
        }
    }
}

// ---------------------------------------------------------------------------
// Flash attention (unchanged fp32 baseline): one CTA = 64 query rows.
// ---------------------------------------------------------------------------
__global__ __launch_bounds__(256) void flash_attn(float* __restrict__ Out) {
    __shared__ float QsT[64][64];
    __shared__ float KsT[64][64];
    __shared__ float Vs[64][64];

    const int tid = threadIdx.x;
    const int ty = tid >> 4;
    const int tx = tid & 15;
    const int q0 = blockIdx.x << 6;
    const int h  = blockIdx.y;
    const int b  = blockIdx.z;

    const size_t baseQ  = ((size_t)(b * T_ + q0) * H_ + h) * E_;
    const size_t baseKV = ((size_t)b * T_ * H_ + h) * E_;

    for (int idx = tid; idx < 1024; idx += 256) {
        int row = idx >> 4;
        int c = (idx & 15) << 2;
        float4 v = *(const float4*)(g_Q + baseQ + (size_t)row * HE_ + c);
        QsT[c + 0][row] = v.x;
        QsT[c + 1][row] = v.y;
        QsT[c + 2][row] = v.z;
        QsT[c + 3][row] = v.w;
    }

    float m[4], l[4], o[4][4];
#pragma unroll
    for (int i = 0; i < 4; i++) {
        m[i] = -1e30f;
        l[i] = 0.f;
#pragma unroll
        for (int j = 0; j < 4; j++) o[i][j] = 0.f;
    }

    for (int k0 = 0; k0 < T_; k0 += 64) {
        __syncthreads();
        for (int idx = tid; idx < 1024; idx += 256) {
            int row = idx >> 4;
            int c = (idx & 15) << 2;
            size_t g = baseKV + (size_t)(k0 + row) * HE_ + c;
            float4 kv = *(const float4*)(g_K + g);
            KsT[c + 0][row] = kv.x;
            KsT[c + 1][row] = kv.y;
            KsT[c + 2][row] = kv.z;
            KsT[c + 3][row] = kv.w;
            *(float4*)&Vs[row][c] = *(const float4*)(g_V + g);
        }
        __syncthreads();

        float s[4][4] = {};
#pragma unroll 16
        for (int e = 0; e < 64; e++) {
            float4 q4 = *(const float4*)&QsT[e][ty << 2];
            float4 k4 = *(const float4*)&KsT[e][tx << 2];
            float q[4] = {q4.x, q4.y, q4.z, q4.w};
            float k[4] = {k4.x, k4.y, k4.z, k4.w};
#pragma unroll
            for (int i = 0; i < 4; i++)
#pragma unroll
                for (int j = 0; j < 4; j++) s[i][j] += q[i] * k[j];
        }

#pragma unroll
        for (int i = 0; i < 4; i++) {
            float mx = fmaxf(fmaxf(s[i][0], s[i][1]), fmaxf(s[i][2], s[i][3]));
#pragma unroll
            for (int off = 8; off >= 1; off >>= 1)
                mx = fmaxf(mx, __shfl_xor_sync(0xffffffffu, mx, off));
            float mnew = fmaxf(m[i], mx);
            float corr = __expf(m[i] - mnew);
            float rs = 0.f;
#pragma unroll
            for (int j = 0; j < 4; j++) {
                s[i][j] = __expf(s[i][j] - mnew);
                rs += s[i][j];
            }
#pragma unroll
            for (int off = 8; off >= 1; off >>= 1)
                rs += __shfl_xor_sync(0xffffffffu, rs, off);
            l[i] = l[i] * corr + rs;
            m[i] = mnew;
#pragma unroll
            for (int j = 0; j < 4; j++) o[i][j] *= corr;
        }

        __syncthreads();
#pragma unroll
        for (int i = 0; i < 4; i++)
            *(float4*)&KsT[(ty << 2) + i][tx << 2] =
                make_float4(s[i][0], s[i][1], s[i][2], s[i][3]);
        __syncthreads();

#pragma unroll 16
        for (int k = 0; k < 64; k++) {
            float4 v4 = *(const float4*)&Vs[k][tx << 2];
            float vv[4] = {v4.x, v4.y, v4.z, v4.w};
#pragma unroll
            for (int i = 0; i < 4; i++) {
                float p = KsT[(ty << 2) + i][k];
#pragma unroll
                for (int j = 0; j < 4; j++) o[i][j] += p * vv[j];
            }
        }
    }

#pragma unroll
    for (int i = 0; i < 4; i++) {
        float inv = 1.0f / l[i];
        float4 r = make_float4(o[i][0] * inv, o[i][1] * inv,
                               o[i][2] * inv, o[i][3] * inv);
        *(float4*)&Out[((size_t)(b * T_ + q0 + (ty << 2) + i) * H_ + h) * E_ +
                       (tx << 2)] = r;
    }
}

// ---------------------------------------------------------------------------
extern "C" void kernel_launch(void* const* d_in, const int* in_sizes, int n_in,
                              void* d_out, int out_size) {
    const float* query     = (const float*)d_in[0];
    const float* key_value = (const float*)d_in[1];
    const float* Wq        = (const float*)d_in[2];
    const float* Wk        = (const float*)d_in[3];
    const float* Wv        = (const float*)d_in[4];
    float* out = (float*)d_out;

    const float scale = 0.35355339059327379f;  // 64^(-1/4)
    const int n4 = BT_ * HIN_ / 4;

    split_act<<<(n4 + 255) / 256, 256>>>((const float4*)query, 0, n4);
    split_act<<<(n4 + 255) / 256, 256>>>((const float4*)key_value, 1, n4);

    dim3 tg(HE_ / 32, HIN_ / 32);
    dim3 tb(32, 8);
    transpose_split<<<tg, tb>>>(Wq, 0);
    transpose_split<<<tg, tb>>>(Wk, 1);
    transpose_split<<<tg, tb>>>(Wv, 2);

    dim3 gproj(HE_ / 128, BT_ / 128);          // (8, 64)
    proj_mma<<<gproj, 256>>>(0, scale);
    proj_mma<<<gproj, 256>>>(1, scale);
    proj_mma<<<gproj, 256>>>(2, 1.0f);

    dim3 gattn(T_ / 64, H_, B_);               // (32, 16, 4)
    flash_attn<<<gattn, 256>>>(out);
}

// round 5
// speedup vs baseline: 1.3498x; 1.3498x over previous
#include <cuda_runtime.h>
#include <cstdint>

#define B_   4
#define T_   2048
#define HIN_ 1024
#define H_   16
#define E_   64
#define HE_  (H_ * E_)   // 1024
#define BT_  (B_ * T_)   // 8192

// Persistent scratch (no allocations allowed in kernel_launch).
__device__ float g_Q[BT_ * HE_];
__device__ float g_K[BT_ * HE_];
__device__ float g_V[BT_ * HE_];

// ---------------------------------------------------------------------------
// Packed fp32x2 helpers (Blackwell FFMA2 — only reachable via PTX f32x2)
// ---------------------------------------------------------------------------
typedef unsigned long long u64;

__device__ __forceinline__ u64 pack2(float lo, float hi) {
    u64 r;
    asm("mov.b64 %0, {%1,%2};" : "=l"(r) : "f"(lo), "f"(hi));
    return r;
}
__device__ __forceinline__ float2 unpack2(u64 v) {
    float2 r;
    asm("mov.b64 {%0,%1}, %2;" : "=f"(r.x), "=f"(r.y) : "l"(v));
    return r;
}
__device__ __forceinline__ void fma2(u64& d, u64 a, u64 b) {
    asm("fma.rn.f32x2 %0, %1, %2, %0;" : "+l"(d) : "l"(a), "l"(b));
}
__device__ __forceinline__ u64 mul2(u64 a, u64 b) {
    u64 r;
    asm("mul.rn.f32x2 %0, %1, %2;" : "=l"(r) : "l"(a), "l"(b));
    return r;
}

// ---------------------------------------------------------------------------
// Projection GEMM: C[M=8192, N=1024] = A[M, K=1024] @ W[K, N], C *= scale
// 64x64 CTA tile, BK=16, 256 threads, 4x4 micro-tile (packed 4x2xf32x2).
// ---------------------------------------------------------------------------
__global__ __launch_bounds__(256) void proj_gemm(const float* __restrict__ A,
                                                 const float* __restrict__ W,
                                                 int sel, float scale) {
    __shared__ float AsT[16][64];   // A tile transposed: [k][m]
    __shared__ float Ws[16][64];    // W tile natural:    [k][n]

    float* __restrict__ C = (sel == 0) ? g_Q : (sel == 1) ? g_K : g_V;

    const int tid = threadIdx.x;
    const int ty = tid >> 4;          // 0..15
    const int tx = tid & 15;          // 0..15
    const int bm = blockIdx.y << 6;
    const int bn = blockIdx.x << 6;

    const int ar = tid >> 2;              // 0..63
    const int ac = (tid & 3) << 2;        // 0,4,8,12
    const int wr = tid >> 4;              // 0..15
    const int wc = (tid & 15) << 2;       // 0..60

    const float* Ap = A + (size_t)(bm + ar) * HIN_ + ac;
    const float* Wp = W + (size_t)wr * HE_ + bn + wc;

    u64 acc[4][2];
#pragma unroll
    for (int i = 0; i < 4; i++) { acc[i][0] = 0ull; acc[i][1] = 0ull; }

    for (int k0 = 0; k0 < HIN_; k0 += 16) {
        float4 av = *(const float4*)(Ap + k0);
        float4 wv = *(const float4*)(Wp + (size_t)k0 * HE_);
        __syncthreads();
        AsT[ac + 0][ar] = av.x;
        AsT[ac + 1][ar] = av.y;
        AsT[ac + 2][ar] = av.z;
        AsT[ac + 3][ar] = av.w;
        *(float4*)&Ws[wr][wc] = wv;
        __syncthreads();

#pragma unroll
        for (int kk = 0; kk < 16; kk++) {
            float4 a4 = *(const float4*)&AsT[kk][ty << 2];   // broadcast
            float4 w4 = *(const float4*)&Ws[kk][tx << 2];    // span
            u64 w0 = pack2(w4.x, w4.y);
            u64 w1 = pack2(w4.z, w4.w);
            float a[4] = {a4.x, a4.y, a4.z, a4.w};
#pragma unroll
            for (int i = 0; i < 4; i++) {
                u64 ad = pack2(a[i], a[i]);
                fma2(acc[i][0], ad, w0);
                fma2(acc[i][1], ad, w1);
            }
        }
    }

#pragma unroll
    for (int i = 0; i < 4; i++) {
        float2 p0 = unpack2(acc[i][0]);
        float2 p1 = unpack2(acc[i][1]);
        float4 r = make_float4(p0.x * scale, p0.y * scale,
                               p1.x * scale, p1.y * scale);
        *(float4*)&C[(size_t)(bm + (ty << 2) + i) * HE_ + bn + (tx << 2)] = r;
    }
}

// ---------------------------------------------------------------------------
// Flash attention: one CTA = 64 query rows for a fixed (b, h).
// 32 key tiles of 64; online softmax; packed f32x2 in QK and PV loops.
// ---------------------------------------------------------------------------
__global__ __launch_bounds__(256) void flash_attn(float* __restrict__ Out) {
    __shared__ float QsT[64][64];   // [e][qrow]
    __shared__ float KsT[64][64];   // [e][krow], reused as P[qrow][krow]
    __shared__ float Vs[64][64];    // [krow][e]

    const int tid = threadIdx.x;
    const int ty = tid >> 4;        // q-row group 0..15
    const int tx = tid & 15;        // col group 0..15
    const int q0 = blockIdx.x << 6;
    const int h  = blockIdx.y;
    const int b  = blockIdx.z;

    const size_t baseQ  = ((size_t)(b * T_ + q0) * H_ + h) * E_;
    const size_t baseKV = ((size_t)b * T_ * H_ + h) * E_;

    for (int idx = tid; idx < 1024; idx += 256) {
        int row = idx >> 4;
        int c = (idx & 15) << 2;
        float4 v = *(const float4*)(g_Q + baseQ + (size_t)row * HE_ + c);
        QsT[c + 0][row] = v.x;
        QsT[c + 1][row] = v.y;
        QsT[c + 2][row] = v.z;
        QsT[c + 3][row] = v.w;
    }

    float m[4], l[4];
    u64 o2[4][2];
#pragma unroll
    for (int i = 0; i < 4; i++) {
        m[i] = -1e30f;
        l[i] = 0.f;
        o2[i][0] = 0ull;
        o2[i][1] = 0ull;
    }

    for (int k0 = 0; k0 < T_; k0 += 64) {
        __syncthreads();
        for (int idx = tid; idx < 1024; idx += 256) {
            int row = idx >> 4;
            int c = (idx & 15) << 2;
            size_t g = baseKV + (size_t)(k0 + row) * HE_ + c;
            float4 kv = *(const float4*)(g_K + g);
            KsT[c + 0][row] = kv.x;
            KsT[c + 1][row] = kv.y;
            KsT[c + 2][row] = kv.z;
            KsT[c + 3][row] = kv.w;
            *(float4*)&Vs[row][c] = *(const float4*)(g_V + g);
        }
        __syncthreads();

        // S = Q K^T (packed outer products over e)
        u64 s2[4][2];
#pragma unroll
        for (int i = 0; i < 4; i++) { s2[i][0] = 0ull; s2[i][1] = 0ull; }
#pragma unroll 16
        for (int e = 0; e < 64; e++) {
            float4 q4 = *(const float4*)&QsT[e][ty << 2];   // broadcast
            float4 k4 = *(const float4*)&KsT[e][tx << 2];   // span
            u64 kp0 = pack2(k4.x, k4.y);
            u64 kp1 = pack2(k4.z, k4.w);
            float q[4] = {q4.x, q4.y, q4.z, q4.w};
#pragma unroll
            for (int i = 0; i < 4; i++) {
                u64 qd = pack2(q[i], q[i]);
                fma2(s2[i][0], qd, kp0);
                fma2(s2[i][1], qd, kp1);
            }
        }

        // Online softmax (scalar; reduce across 16 tx lanes per q row)
        float s[4][4];
#pragma unroll
        for (int i = 0; i < 4; i++) {
            float2 p0 = unpack2(s2[i][0]);
            float2 p1 = unpack2(s2[i][1]);
            s[i][0] = p0.x; s[i][1] = p0.y; s[i][2] = p1.x; s[i][3] = p1.y;
        }
#pragma unroll
        for (int i = 0; i < 4; i++) {
            float mx = fmaxf(fmaxf(s[i][0], s[i][1]), fmaxf(s[i][2], s[i][3]));
#pragma unroll
            for (int off = 8; off >= 1; off >>= 1)
                mx = fmaxf(mx, __shfl_xor_sync(0xffffffffu, mx, off));
            float mnew = fmaxf(m[i], mx);
            float corr = __expf(m[i] - mnew);
            float rs = 0.f;
#pragma unroll
            for (int j = 0; j < 4; j++) {
                s[i][j] = __expf(s[i][j] - mnew);
                rs += s[i][j];
            }
#pragma unroll
            for (int off = 8; off >= 1; off >>= 1)
                rs += __shfl_xor_sync(0xffffffffu, rs, off);
            l[i] = l[i] * corr + rs;
            m[i] = mnew;
            u64 cd = pack2(corr, corr);
            o2[i][0] = mul2(o2[i][0], cd);
            o2[i][1] = mul2(o2[i][1], cd);
        }

        __syncthreads();   // done reading KsT as K
#pragma unroll
        for (int i = 0; i < 4; i++)
            *(float4*)&KsT[(ty << 2) + i][tx << 2] =
                make_float4(s[i][0], s[i][1], s[i][2], s[i][3]);
        __syncthreads();   // P visible

        // O += P @ V (packed)
#pragma unroll 16
        for (int k = 0; k < 64; k++) {
            float4 v4 = *(const float4*)&Vs[k][tx << 2];
            u64 vp0 = pack2(v4.x, v4.y);
            u64 vp1 = pack2(v4.z, v4.w);
#pragma unroll
            for (int i = 0; i < 4; i++) {
                float p = KsT[(ty << 2) + i][k];   // broadcast
                u64 pd = pack2(p, p);
                fma2(o2[i][0], pd, vp0);
                fma2(o2[i][1], pd, vp1);
            }
        }
    }

#pragma unroll
    for (int i = 0; i < 4; i++) {
        float inv = 1.0f / l[i];
        float2 p0 = unpack2(o2[i][0]);
        float2 p1 = unpack2(o2[i][1]);
        float4 r = make_float4(p0.x * inv, p0.y * inv, p1.x * inv, p1.y * inv);
        *(float4*)&Out[((size_t)(b * T_ + q0 + (ty << 2) + i) * H_ + h) * E_ +
                       (tx << 2)] = r;
    }
}

// ---------------------------------------------------------------------------
extern "C" void kernel_launch(void* const* d_in, const int* in_sizes, int n_in,
                              void* d_out, int out_size) {
    const float* query     = (const float*)d_in[0];
    const float* key_value = (const float*)d_in[1];
    const float* Wq        = (const float*)d_in[2];
    const float* Wk        = (const float*)d_in[3];
    const float* Wv        = (const float*)d_in[4];
    float* out = (float*)d_out;

    const float scale = 0.35355339059327379f;  // 64^(-1/4)

    dim3 gproj(HE_ / 64, BT_ / 64);            // (16, 128)
    proj_gemm<<<gproj, 256>>>(query,     Wq, 0, scale);
    proj_gemm<<<gproj, 256>>>(key_value, Wk, 1, scale);
    proj_gemm<<<gproj, 256>>>(key_value, Wv, 2, 1.0f);

    dim3 gattn(T_ / 64, H_, B_);               // (32, 16, 4)
    flash_attn<<<gattn, 256>>>(out);
}

// round 6
// speedup vs baseline: 1.5496x; 1.1480x over previous
#include <cuda_runtime.h>
#include <cstdint>

#define B_   4
#define T_   2048
#define HIN_ 1024
#define H_   16
#define E_   64
#define HE_  (H_ * E_)   // 1024
#define BT_  (B_ * T_)   // 8192

// Persistent scratch (no allocations allowed in kernel_launch).
__device__ float g_Q[BT_ * HE_];
__device__ float g_K[BT_ * HE_];
__device__ float g_V[BT_ * HE_];

// ---------------------------------------------------------------------------
// Packed fp32x2 helpers (Blackwell FFMA2 via PTX f32x2)
// ---------------------------------------------------------------------------
typedef unsigned long long u64;

__device__ __forceinline__ u64 pack2(float lo, float hi) {
    u64 r;
    asm("mov.b64 %0, {%1,%2};" : "=l"(r) : "f"(lo), "f"(hi));
    return r;
}
__device__ __forceinline__ float2 unpack2(u64 v) {
    float2 r;
    asm("mov.b64 {%0,%1}, %2;" : "=f"(r.x), "=f"(r.y) : "l"(v));
    return r;
}
__device__ __forceinline__ void fma2(u64& d, u64 a, u64 b) {
    asm("fma.rn.f32x2 %0, %1, %2, %0;" : "+l"(d) : "l"(a), "l"(b));
}
__device__ __forceinline__ u64 mul2(u64 a, u64 b) {
    u64 r;
    asm("mul.rn.f32x2 %0, %1, %2;" : "=l"(r) : "l"(a), "l"(b));
    return r;
}

// ---------------------------------------------------------------------------
// Projection GEMM: C[M=8192, N=1024] = A[M, K=1024] @ W[K, N], C *= scale
// 64x64 CTA tile, BK=16, 128 threads, 8x4 micro-tile per thread.
// Span loads (W) reused across 8 rows; A loads are 16-lane broadcasts.
// ---------------------------------------------------------------------------
__global__ __launch_bounds__(128) void proj_gemm(const float* __restrict__ A,
                                                 const float* __restrict__ W,
                                                 int sel, float scale) {
    __shared__ float AsT[16][64];   // A tile transposed: [k][m]
    __shared__ float Ws[16][64];    // W tile natural:    [k][n]

    float* __restrict__ C = (sel == 0) ? g_Q : (sel == 1) ? g_K : g_V;

    const int tid = threadIdx.x;
    const int ty = tid >> 4;          // 0..7  (8 q rows each)
    const int tx = tid & 15;          // 0..15 (4 cols each)
    const int bm = blockIdx.y << 6;
    const int bn = blockIdx.x << 6;

    // A loader: 64 rows x 16 cols; thread -> row tid/2, 8 cols at (tid&1)*8
    const int ar = tid >> 1;
    const int ac = (tid & 1) << 3;
    // W loader: 16 rows x 64 cols; thread -> row tid/8, 8 cols at (tid&7)*8
    const int wr = tid >> 3;
    const int wc = (tid & 7) << 3;

    const float* Ap = A + (size_t)(bm + ar) * HIN_ + ac;
    const float* Wp = W + (size_t)wr * HE_ + bn + wc;

    u64 acc[8][2];
#pragma unroll
    for (int i = 0; i < 8; i++) { acc[i][0] = 0ull; acc[i][1] = 0ull; }

    for (int k0 = 0; k0 < HIN_; k0 += 16) {
        float4 av0 = *(const float4*)(Ap + k0);
        float4 av1 = *(const float4*)(Ap + k0 + 4);
        float4 wv0 = *(const float4*)(Wp + (size_t)k0 * HE_);
        float4 wv1 = *(const float4*)(Wp + (size_t)k0 * HE_ + 4);
        __syncthreads();
        AsT[ac + 0][ar] = av0.x;
        AsT[ac + 1][ar] = av0.y;
        AsT[ac + 2][ar] = av0.z;
        AsT[ac + 3][ar] = av0.w;
        AsT[ac + 4][ar] = av1.x;
        AsT[ac + 5][ar] = av1.y;
        AsT[ac + 6][ar] = av1.z;
        AsT[ac + 7][ar] = av1.w;
        *(float4*)&Ws[wr][wc + 0] = wv0;
        *(float4*)&Ws[wr][wc + 4] = wv1;
        __syncthreads();

#pragma unroll
        for (int kk = 0; kk < 16; kk++) {
            float4 a0 = *(const float4*)&AsT[kk][ty << 3];       // broadcast
            float4 a1 = *(const float4*)&AsT[kk][(ty << 3) + 4]; // broadcast
            float4 w4 = *(const float4*)&Ws[kk][tx << 2];        // span
            u64 w0 = pack2(w4.x, w4.y);
            u64 w1 = pack2(w4.z, w4.w);
            float a[8] = {a0.x, a0.y, a0.z, a0.w, a1.x, a1.y, a1.z, a1.w};
#pragma unroll
            for (int i = 0; i < 8; i++) {
                u64 ad = pack2(a[i], a[i]);
                fma2(acc[i][0], ad, w0);
                fma2(acc[i][1], ad, w1);
            }
        }
    }

#pragma unroll
    for (int i = 0; i < 8; i++) {
        float2 p0 = unpack2(acc[i][0]);
        float2 p1 = unpack2(acc[i][1]);
        float4 r = make_float4(p0.x * scale, p0.y * scale,
                               p1.x * scale, p1.y * scale);
        *(float4*)&C[(size_t)(bm + (ty << 3) + i) * HE_ + bn + (tx << 2)] = r;
    }
}

// ---------------------------------------------------------------------------
// Flash attention: one CTA (128 threads) = 64 query rows for a fixed (b, h).
// 32 key tiles of 64; online softmax; 8x4 micro-tile; span loads halved.
// ---------------------------------------------------------------------------
__global__ __launch_bounds__(128) void flash_attn(float* __restrict__ Out) {
    __shared__ float QsT[64][64];   // [e][qrow]
    __shared__ float KsT[64][64];   // [e][krow], reused as P[qrow][krow]
    __shared__ float Vs[64][64];    // [krow][e]

    const int tid = threadIdx.x;
    const int ty = tid >> 4;        // q-row group 0..7 (8 rows each)
    const int tx = tid & 15;        // col group 0..15 (4 cols each)
    const int q0 = blockIdx.x << 6;
    const int h  = blockIdx.y;
    const int b  = blockIdx.z;

    const size_t baseQ  = ((size_t)(b * T_ + q0) * H_ + h) * E_;
    const size_t baseKV = ((size_t)b * T_ * H_ + h) * E_;

    for (int idx = tid; idx < 1024; idx += 128) {
        int row = idx >> 4;
        int c = (idx & 15) << 2;
        float4 v = *(const float4*)(g_Q + baseQ + (size_t)row * HE_ + c);
        QsT[c + 0][row] = v.x;
        QsT[c + 1][row] = v.y;
        QsT[c + 2][row] = v.z;
        QsT[c + 3][row] = v.w;
    }

    float m[8], l[8];
    u64 o2[8][2];
#pragma unroll
    for (int i = 0; i < 8; i++) {
        m[i] = -1e30f;
        l[i] = 0.f;
        o2[i][0] = 0ull;
        o2[i][1] = 0ull;
    }

    for (int k0 = 0; k0 < T_; k0 += 64) {
        __syncthreads();
        for (int idx = tid; idx < 1024; idx += 128) {
            int row = idx >> 4;
            int c = (idx & 15) << 2;
            size_t g = baseKV + (size_t)(k0 + row) * HE_ + c;
            float4 kv = *(const float4*)(g_K + g);
            KsT[c + 0][row] = kv.x;
            KsT[c + 1][row] = kv.y;
            KsT[c + 2][row] = kv.z;
            KsT[c + 3][row] = kv.w;
            *(float4*)&Vs[row][c] = *(const float4*)(g_V + g);
        }
        __syncthreads();

        // S = Q K^T: 8x4 outer products over e
        u64 s2[8][2];
#pragma unroll
        for (int i = 0; i < 8; i++) { s2[i][0] = 0ull; s2[i][1] = 0ull; }
#pragma unroll 8
        for (int e = 0; e < 64; e++) {
            float4 qa = *(const float4*)&QsT[e][ty << 3];        // broadcast
            float4 qb = *(const float4*)&QsT[e][(ty << 3) + 4];  // broadcast
            float4 k4 = *(const float4*)&KsT[e][tx << 2];        // span
            u64 kp0 = pack2(k4.x, k4.y);
            u64 kp1 = pack2(k4.z, k4.w);
            float q[8] = {qa.x, qa.y, qa.z, qa.w, qb.x, qb.y, qb.z, qb.w};
#pragma unroll
            for (int i = 0; i < 8; i++) {
                u64 qd = pack2(q[i], q[i]);
                fma2(s2[i][0], qd, kp0);
                fma2(s2[i][1], qd, kp1);
            }
        }

        // Online softmax: reduce across the 16 tx lanes per q row
        float s[8][4];
#pragma unroll
        for (int i = 0; i < 8; i++) {
            float2 p0 = unpack2(s2[i][0]);
            float2 p1 = unpack2(s2[i][1]);
            s[i][0] = p0.x; s[i][1] = p0.y; s[i][2] = p1.x; s[i][3] = p1.y;
        }
#pragma unroll
        for (int i = 0; i < 8; i++) {
            float mx = fmaxf(fmaxf(s[i][0], s[i][1]), fmaxf(s[i][2], s[i][3]));
#pragma unroll
            for (int off = 8; off >= 1; off >>= 1)
                mx = fmaxf(mx, __shfl_xor_sync(0xffffffffu, mx, off));
            float mnew = fmaxf(m[i], mx);
            float corr = __expf(m[i] - mnew);
            float rs = 0.f;
#pragma unroll
            for (int j = 0; j < 4; j++) {
                s[i][j] = __expf(s[i][j] - mnew);
                rs += s[i][j];
            }
#pragma unroll
            for (int off = 8; off >= 1; off >>= 1)
                rs += __shfl_xor_sync(0xffffffffu, rs, off);
            l[i] = l[i] * corr + rs;
            m[i] = mnew;
            u64 cd = pack2(corr, corr);
            o2[i][0] = mul2(o2[i][0], cd);
            o2[i][1] = mul2(o2[i][1], cd);
        }

        __syncthreads();   // done reading KsT as K
#pragma unroll
        for (int i = 0; i < 8; i++)
            *(float4*)&KsT[(ty << 3) + i][tx << 2] =
                make_float4(s[i][0], s[i][1], s[i][2], s[i][3]);
        __syncthreads();   // P visible

        // O += P @ V  (k unrolled by 4; p reads are float4 broadcasts)
#pragma unroll 4
        for (int k = 0; k < 64; k += 4) {
            u64 vp[4][2];
#pragma unroll
            for (int kk = 0; kk < 4; kk++) {
                float4 v4 = *(const float4*)&Vs[k + kk][tx << 2];  // span
                vp[kk][0] = pack2(v4.x, v4.y);
                vp[kk][1] = pack2(v4.z, v4.w);
            }
#pragma unroll
            for (int i = 0; i < 8; i++) {
                float4 p4 = *(const float4*)&KsT[(ty << 3) + i][k]; // broadcast
                float p[4] = {p4.x, p4.y, p4.z, p4.w};
#pragma unroll
                for (int kk = 0; kk < 4; kk++) {
                    u64 pd = pack2(p[kk], p[kk]);
                    fma2(o2[i][0], pd, vp[kk][0]);
                    fma2(o2[i][1], pd, vp[kk][1]);
                }
            }
        }
    }

#pragma unroll
    for (int i = 0; i < 8; i++) {
        float inv = 1.0f / l[i];
        float2 p0 = unpack2(o2[i][0]);
        float2 p1 = unpack2(o2[i][1]);
        float4 r = make_float4(p0.x * inv, p0.y * inv, p1.x * inv, p1.y * inv);
        *(float4*)&Out[((size_t)(b * T_ + q0 + (ty << 3) + i) * H_ + h) * E_ +
                       (tx << 2)] = r;
    }
}

// ---------------------------------------------------------------------------
extern "C" void kernel_launch(void* const* d_in, const int* in_sizes, int n_in,
                              void* d_out, int out_size) {
    const float* query     = (const float*)d_in[0];
    const float* key_value = (const float*)d_in[1];
    const float* Wq        = (const float*)d_in[2];
    const float* Wk        = (const float*)d_in[3];
    const float* Wv        = (const float*)d_in[4];
    float* out = (float*)d_out;

    const float scale = 0.35355339059327379f;  // 64^(-1/4)

    dim3 gproj(HE_ / 64, BT_ / 64);            // (16, 128)
    proj_gemm<<<gproj, 128>>>(query,     Wq, 0, scale);
    proj_gemm<<<gproj, 128>>>(key_value, Wk, 1, scale);
    proj_gemm<<<gproj, 128>>>(key_value, Wv, 2, 1.0f);

    dim3 gattn(T_ / 64, H_, B_);               // (32, 16, 4)
    flash_attn<<<gattn, 128>>>(out);
}

// round 7
// speedup vs baseline: 1.6821x; 1.0855x over previous
#include <cuda_runtime.h>
#include <cstdint>

#define B_   4
#define T_   2048
#define HIN_ 1024
#define H_   16
#define E_   64
#define HE_  (H_ * E_)   // 1024
#define BT_  (B_ * T_)   // 8192

// Persistent scratch (no allocations allowed in kernel_launch).
__device__ float g_Q[BT_ * HE_];
__device__ float g_K[BT_ * HE_];
__device__ float g_V[BT_ * HE_];

// ---------------------------------------------------------------------------
// Packed fp32x2 helpers (Blackwell FFMA2 via PTX f32x2)
// ---------------------------------------------------------------------------
typedef unsigned long long u64;

__device__ __forceinline__ u64 pack2(float lo, float hi) {
    u64 r;
    asm("mov.b64 %0, {%1,%2};" : "=l"(r) : "f"(lo), "f"(hi));
    return r;
}
__device__ __forceinline__ float2 unpack2(u64 v) {
    float2 r;
    asm("mov.b64 {%0,%1}, %2;" : "=f"(r.x), "=f"(r.y) : "l"(v));
    return r;
}
__device__ __forceinline__ void fma2(u64& d, u64 a, u64 b) {
    asm("fma.rn.f32x2 %0, %1, %2, %0;" : "+l"(d) : "l"(a), "l"(b));
}
__device__ __forceinline__ u64 mul2(u64 a, u64 b) {
    u64 r;
    asm("mul.rn.f32x2 %0, %1, %2;" : "=l"(r) : "l"(a), "l"(b));
    return r;
}

// ---------------------------------------------------------------------------
// Projection GEMM: C[M=8192, N=1024] = A[M, K=1024] @ W[K, N], C *= scale
// 64x64 CTA tile, BK=16, 128 threads, 8x4 micro-tile per thread. (R6 kernel)
// ---------------------------------------------------------------------------
__global__ __launch_bounds__(128) void proj_gemm(const float* __restrict__ A,
                                                 const float* __restrict__ W,
                                                 int sel, float scale) {
    __shared__ float AsT[16][64];   // A tile transposed: [k][m]
    __shared__ float Ws[16][64];    // W tile natural:    [k][n]

    float* __restrict__ C = (sel == 0) ? g_Q : (sel == 1) ? g_K : g_V;

    const int tid = threadIdx.x;
    const int ty = tid >> 4;          // 0..7
    const int tx = tid & 15;          // 0..15
    const int bm = blockIdx.y << 6;
    const int bn = blockIdx.x << 6;

    const int ar = tid >> 1;
    const int ac = (tid & 1) << 3;
    const int wr = tid >> 3;
    const int wc = (tid & 7) << 3;

    const float* Ap = A + (size_t)(bm + ar) * HIN_ + ac;
    const float* Wp = W + (size_t)wr * HE_ + bn + wc;

    u64 acc[8][2];
#pragma unroll
    for (int i = 0; i < 8; i++) { acc[i][0] = 0ull; acc[i][1] = 0ull; }

    for (int k0 = 0; k0 < HIN_; k0 += 16) {
        float4 av0 = *(const float4*)(Ap + k0);
        float4 av1 = *(const float4*)(Ap + k0 + 4);
        float4 wv0 = *(const float4*)(Wp + (size_t)k0 * HE_);
        float4 wv1 = *(const float4*)(Wp + (size_t)k0 * HE_ + 4);
        __syncthreads();
        AsT[ac + 0][ar] = av0.x;
        AsT[ac + 1][ar] = av0.y;
        AsT[ac + 2][ar] = av0.z;
        AsT[ac + 3][ar] = av0.w;
        AsT[ac + 4][ar] = av1.x;
        AsT[ac + 5][ar] = av1.y;
        AsT[ac + 6][ar] = av1.z;
        AsT[ac + 7][ar] = av1.w;
        *(float4*)&Ws[wr][wc + 0] = wv0;
        *(float4*)&Ws[wr][wc + 4] = wv1;
        __syncthreads();

#pragma unroll
        for (int kk = 0; kk < 16; kk++) {
            float4 a0 = *(const float4*)&AsT[kk][ty << 3];
            float4 a1 = *(const float4*)&AsT[kk][(ty << 3) + 4];
            float4 w4 = *(const float4*)&Ws[kk][tx << 2];
            u64 w0 = pack2(w4.x, w4.y);
            u64 w1 = pack2(w4.z, w4.w);
            float a[8] = {a0.x, a0.y, a0.z, a0.w, a1.x, a1.y, a1.z, a1.w};
#pragma unroll
            for (int i = 0; i < 8; i++) {
                u64 ad = pack2(a[i], a[i]);
                fma2(acc[i][0], ad, w0);
                fma2(acc[i][1], ad, w1);
            }
        }
    }

#pragma unroll
    for (int i = 0; i < 8; i++) {
        float2 p0 = unpack2(acc[i][0]);
        float2 p1 = unpack2(acc[i][1]);
        float4 r = make_float4(p0.x * scale, p0.y * scale,
                               p1.x * scale, p1.y * scale);
        *(float4*)&C[(size_t)(bm + (ty << 3) + i) * HE_ + bn + (tx << 2)] = r;
    }
}

// ---------------------------------------------------------------------------
// Flash attention: one CTA (128 threads) = 64 query rows for a fixed (b, h).
// Transposed Q/K tiles use an XOR swizzle on the row-column so the
// transpose STORES are ~2-way instead of 16-way bank-conflicted:
//   storage col of (e, r) = (((r>>2) ^ ((e>>2)&15)) << 2) | (r&3)
// Span reads remain conflict-free float4 permutations of the 64 columns.
// KsT is reused (plain layout) for P between syncthreads.
// ---------------------------------------------------------------------------
__global__ __launch_bounds__(128) void flash_attn(float* __restrict__ Out) {
    __shared__ float QsT[64][64];   // swizzled [e][qrow]
    __shared__ float KsT[64][64];   // swizzled [e][krow]; reused plain as P
    __shared__ float Vs[64][64];    // [krow][e]

    const int tid = threadIdx.x;
    const int ty = tid >> 4;        // q-row group 0..7 (8 rows each)
    const int tx = tid & 15;        // col group 0..15 (4 cols each)
    const int q0 = blockIdx.x << 6;
    const int h  = blockIdx.y;
    const int b  = blockIdx.z;

    const size_t baseQ  = ((size_t)(b * T_ + q0) * H_ + h) * E_;
    const size_t baseKV = ((size_t)b * T_ * H_ + h) * E_;

    // Load Q tile transposed+swizzled (once per CTA)
    for (int idx = tid; idx < 1024; idx += 128) {
        int row = idx >> 4;             // qrow
        int t = idx & 15;               // e-group: e = 4t..4t+3
        int c = t << 2;
        float4 v = *(const float4*)(g_Q + baseQ + (size_t)row * HE_ + c);
        int col = (((row >> 2) ^ t) << 2) | (row & 3);
        QsT[c + 0][col] = v.x;
        QsT[c + 1][col] = v.y;
        QsT[c + 2][col] = v.z;
        QsT[c + 3][col] = v.w;
    }

    float m[8], l[8];
    u64 o2[8][2];
#pragma unroll
    for (int i = 0; i < 8; i++) {
        m[i] = -1e30f;
        l[i] = 0.f;
        o2[i][0] = 0ull;
        o2[i][1] = 0ull;
    }

    for (int k0 = 0; k0 < T_; k0 += 64) {
        __syncthreads();
        for (int idx = tid; idx < 1024; idx += 128) {
            int row = idx >> 4;         // krow
            int t = idx & 15;           // e-group
            int c = t << 2;
            size_t g = baseKV + (size_t)(k0 + row) * HE_ + c;
            float4 kv = *(const float4*)(g_K + g);
            int col = (((row >> 2) ^ t) << 2) | (row & 3);
            KsT[c + 0][col] = kv.x;
            KsT[c + 1][col] = kv.y;
            KsT[c + 2][col] = kv.z;
            KsT[c + 3][col] = kv.w;
            *(float4*)&Vs[row][c] = *(const float4*)(g_V + g);
        }
        __syncthreads();

        // S = Q K^T: 8x4 outer products over e (swizzled reads)
        u64 s2[8][2];
#pragma unroll
        for (int i = 0; i < 8; i++) { s2[i][0] = 0ull; s2[i][1] = 0ull; }
#pragma unroll 4
        for (int x = 0; x < 16; x++) {          // e-group
#pragma unroll
            for (int ee = 0; ee < 4; ee++) {
                int e = (x << 2) + ee;
                float4 qa = *(const float4*)&QsT[e][((2 * ty) ^ x) << 2];
                float4 qb = *(const float4*)&QsT[e][((2 * ty + 1) ^ x) << 2];
                float4 k4 = *(const float4*)&KsT[e][(tx ^ x) << 2];
                u64 kp0 = pack2(k4.x, k4.y);
                u64 kp1 = pack2(k4.z, k4.w);
                float q[8] = {qa.x, qa.y, qa.z, qa.w, qb.x, qb.y, qb.z, qb.w};
#pragma unroll
                for (int i = 0; i < 8; i++) {
                    u64 qd = pack2(q[i], q[i]);
                    fma2(s2[i][0], qd, kp0);
                    fma2(s2[i][1], qd, kp1);
                }
            }
        }

        // Online softmax: reduce across the 16 tx lanes per q row
        float s[8][4];
#pragma unroll
        for (int i = 0; i < 8; i++) {
            float2 p0 = unpack2(s2[i][0]);
            float2 p1 = unpack2(s2[i][1]);
            s[i][0] = p0.x; s[i][1] = p0.y; s[i][2] = p1.x; s[i][3] = p1.y;
        }
#pragma unroll
        for (int i = 0; i < 8; i++) {
            float mx = fmaxf(fmaxf(s[i][0], s[i][1]), fmaxf(s[i][2], s[i][3]));
#pragma unroll
            for (int off = 8; off >= 1; off >>= 1)
                mx = fmaxf(mx, __shfl_xor_sync(0xffffffffu, mx, off));
            float mnew = fmaxf(m[i], mx);
            float corr = __expf(m[i] - mnew);
            float rs = 0.f;
#pragma unroll
            for (int j = 0; j < 4; j++) {
                s[i][j] = __expf(s[i][j] - mnew);
                rs += s[i][j];
            }
#pragma unroll
            for (int off = 8; off >= 1; off >>= 1)
                rs += __shfl_xor_sync(0xffffffffu, rs, off);
            l[i] = l[i] * corr + rs;
            m[i] = mnew;
            u64 cd = pack2(corr, corr);
            o2[i][0] = mul2(o2[i][0], cd);
            o2[i][1] = mul2(o2[i][1], cd);
        }

        __syncthreads();   // done reading KsT as K
#pragma unroll
        for (int i = 0; i < 8; i++)
            *(float4*)&KsT[(ty << 3) + i][tx << 2] =
                make_float4(s[i][0], s[i][1], s[i][2], s[i][3]);
        __syncthreads();   // P visible (plain layout)

        // O += P @ V  (k unrolled by 4; p reads are float4 broadcasts)
#pragma unroll 4
        for (int k = 0; k < 64; k += 4) {
            u64 vp[4][2];
#pragma unroll
            for (int kk = 0; kk < 4; kk++) {
                float4 v4 = *(const float4*)&Vs[k + kk][tx << 2];  // span
                vp[kk][0] = pack2(v4.x, v4.y);
                vp[kk][1] = pack2(v4.z, v4.w);
            }
#pragma unroll
            for (int i = 0; i < 8; i++) {
                float4 p4 = *(const float4*)&KsT[(ty << 3) + i][k]; // broadcast
                float p[4] = {p4.x, p4.y, p4.z, p4.w};
#pragma unroll
                for (int kk = 0; kk < 4; kk++) {
                    u64 pd = pack2(p[kk], p[kk]);
                    fma2(o2[i][0], pd, vp[kk][0]);
                    fma2(o2[i][1], pd, vp[kk][1]);
                }
            }
        }
    }

#pragma unroll
    for (int i = 0; i < 8; i++) {
        float inv = 1.0f / l[i];
        float2 p0 = unpack2(o2[i][0]);
        float2 p1 = unpack2(o2[i][1]);
        float4 r = make_float4(p0.x * inv, p0.y * inv, p1.x * inv, p1.y * inv);
        *(float4*)&Out[((size_t)(b * T_ + q0 + (ty << 3) + i) * H_ + h) * E_ +
                       (tx << 2)] = r;
    }
}

// ---------------------------------------------------------------------------
extern "C" void kernel_launch(void* const* d_in, const int* in_sizes, int n_in,
                              void* d_out, int out_size) {
    const float* query     = (const float*)d_in[0];
    const float* key_value = (const float*)d_in[1];
    const float* Wq        = (const float*)d_in[2];
    const float* Wk        = (const float*)d_in[3];
    const float* Wv        = (const float*)d_in[4];
    float* out = (float*)d_out;

    const float scale = 0.35355339059327379f;  // 64^(-1/4)

    dim3 gproj(HE_ / 64, BT_ / 64);            // (16, 128)
    proj_gemm<<<gproj, 128>>>(query,     Wq, 0, scale);
    proj_gemm<<<gproj, 128>>>(key_value, Wk, 1, scale);
    proj_gemm<<<gproj, 128>>>(key_value, Wv, 2, 1.0f);

    dim3 gattn(T_ / 64, H_, B_);               // (32, 16, 4)
    flash_attn<<<gattn, 128>>>(out);
}